// round 15
// baseline (speedup 1.0000x reference)
#include <cuda_runtime.h>
#include <cstdint>

#define BB 8
#define NN 2048
#define KK 16
#define CIN 64
#define CMID 16
#define COUT 64
#define H1 32
#define H2 32
#define FH1 256
#define NPTS (BB * NN)          // 16384
#define NPAIR (NPTS * KK)       // 262144
#define EDIM (CMID * CIN)       // 1024

// Scratch (device globals: no runtime allocation allowed)
__device__ int   g_idxs[NPAIR];
__device__ float g_M[(size_t)NPAIR * CMID];  // 16 MB  (masked m per pair)
__device__ float g_E[(size_t)NPTS * EDIM];   // 64 MB (tf32-rounded)
__device__ float g_f1T[FH1 * EDIM];          // 1 MB  (f1^T [n][k], tf32)
__device__ float g_f2T[COUT * FH1];          // 64 KB (f2^T [n][k], tf32)

// ===========================================================================
// Helpers (base-ISA PTX only: mma.sync / ldmatrix / cp.async)
// ===========================================================================
__device__ __forceinline__ uint32_t smem_u32(const void* p) {
    uint32_t a;
    asm("{ .reg .u64 t; cvta.to.shared.u64 t, %1; cvt.u32.u64 %0, t; }"
        : "=r"(a) : "l"(p));
    return a;
}
__device__ __forceinline__ float to_tf32(float x) {
    uint32_t r;
    asm("cvt.rna.tf32.f32 %0, %1;" : "=r"(r) : "f"(x));
    return __uint_as_float(r);
}
__device__ __forceinline__ void cpa16(uint32_t dst, const float* src) {
    asm volatile("cp.async.cg.shared.global [%0], [%1], 16;"
                 :: "r"(dst), "l"(__cvta_generic_to_global(src)) : "memory");
}
#define CP_COMMIT() asm volatile("cp.async.commit_group;" ::: "memory")
#define CP_WAIT1()  asm volatile("cp.async.wait_group 1;" ::: "memory")
#define CP_WAIT0()  asm volatile("cp.async.wait_group 0;" ::: "memory")

#define SMEM_SWZ128(off) ((off) ^ (((off) >> 3) & 0x70))
// 1KB-row swizzle (rows of 256 floats = 64 chunks of 16B)
__device__ __forceinline__ uint32_t swz2(int row, int c) {
    return (uint32_t)(row * 1024 + ((c ^ (row & 7)) << 4));
}

#define LDSM4(r0, r1, r2, r3, addr) \
    asm volatile("ldmatrix.sync.aligned.m8n8.x4.shared.b16 {%0,%1,%2,%3}, [%4];" \
                 : "=r"(r0), "=r"(r1), "=r"(r2), "=r"(r3) : "r"(addr))

#define MMA_TF32(d, a, b) \
    asm volatile("mma.sync.aligned.m16n8k8.row.col.f32.tf32.tf32.f32 " \
                 "{%0,%1,%2,%3},{%4,%5,%6,%7},{%8,%9},{%0,%1,%2,%3};" \
                 : "+f"((d)[0]), "+f"((d)[1]), "+f"((d)[2]), "+f"((d)[3]) \
                 : "r"((a)[0]), "r"((a)[1]), "r"((a)[2]), "r"((a)[3]), \
                   "r"((b)[0]), "r"((b)[1]))

// ---------------------------------------------------------------------------
// Kernel 1 (merged prep): neighbor indices + f1/f2 transposes (tf32).
// Grid layout: blocks [0,64)   = idxs  (8 batches x 8 chunks of 256 points)
//              blocks [64,320) = f1 transpose (32 k-tiles x 8 n-tiles)
//              blocks [320,336)= f2 transpose (8 k-tiles x 2 n-tiles)
// ---------------------------------------------------------------------------
__global__ void __launch_bounds__(256) k_prep(
    const int* __restrict__ groups,
    const float* __restrict__ f1, const float* __restrict__ f2)
{
    __shared__ int   sg[NN];
    __shared__ float ts[32][33];
    const int bid = blockIdx.x;
    const int t   = threadIdx.x;

    if (bid < 64) {
        // --- neighbor indices (reference-stable order) ---
        const int b = bid >> 3;
        const int* gr = groups + (size_t)b * NN;
        for (int i = t; i < NN; i += 256) sg[i] = gr[i];
        __syncthreads();

        const int i = (bid & 7) * 256 + t;
        const int g = sg[i];
        const int base = (b * NN + i) * KK;
        int cnt = 0;
        for (int j = 0; j < NN; j++) {
            if (sg[j] == g) {
                g_idxs[base + cnt] = j;
                if (++cnt == KK) break;
            }
        }
        if (cnt < KK) {
            for (int j = 0; j < NN && cnt < KK; j++) {
                if (sg[j] != g) { g_idxs[base + cnt] = j; cnt++; }
            }
        }
    } else if (bid < 320) {
        // --- transpose f1 [1024][256] -> g_f1T [256][1024], tf32-rounded ---
        const int u = bid - 64;
        const int bx = u & 31;       // k-tile 0..31
        const int by = u >> 5;       // n-tile 0..7
        const int x = t & 31;
        const int y = t >> 5;        // 0..7
        #pragma unroll
        for (int s = 0; s < 4; s++) {
            int k = bx * 32 + y + s * 8;
            int n = by * 32 + x;
            ts[y + s * 8][x] = f1[(size_t)k * FH1 + n];
        }
        __syncthreads();
        #pragma unroll
        for (int s = 0; s < 4; s++) {
            int n = by * 32 + y + s * 8;
            int k = bx * 32 + x;
            g_f1T[(size_t)n * EDIM + k] = to_tf32(ts[x][y + s * 8]);
        }
    } else {
        // --- transpose f2 [256][64] -> g_f2T [64][256], tf32-rounded ---
        const int u = bid - 320;
        const int bx = u & 7;        // k-tile 0..7
        const int by = u >> 3;       // n-tile 0..1
        const int x = t & 31;
        const int y = t >> 5;
        #pragma unroll
        for (int s = 0; s < 4; s++) {
            int k = bx * 32 + y + s * 8;
            int n = by * 32 + x;
            ts[y + s * 8][x] = f2[(size_t)k * COUT + n];
        }
        __syncthreads();
        #pragma unroll
        for (int s = 0; s < 4; s++) {
            int n = by * 32 + y + s * 8;
            int k = bx * 32 + x;
            g_f2T[(size_t)n * FH1 + k] = to_tf32(ts[x][y + s * 8]);
        }
    }
}

// ---------------------------------------------------------------------------
// Kernel 2a (tensor MLP): m = relu-MLP(rel) * tmask  -> g_M [pair][16]
// ---------------------------------------------------------------------------
__global__ void __launch_bounds__(256, 2) k_mlp(
    const float* __restrict__ points, const float* __restrict__ mask,
    const float* __restrict__ w1, const float* __restrict__ b1,
    const float* __restrict__ w2, const float* __restrict__ b2,
    const float* __restrict__ w3, const float* __restrict__ b3)
{
    __shared__ float xbuf_all[8 * 1024];   // 8 warps x 4KB
    const int t    = threadIdx.x;
    const int lane = t & 31;
    const int wid  = t >> 5;
    const uint32_t xb = smem_u32(xbuf_all + wid * 1024);

    const int kk = lane & 3;
    const int gg = lane >> 2;

    const int pr = blockIdx.x * 256 + wid * 32 + lane;
    const int p  = pr >> 4;
    const int q  = (p / NN) * NN + g_idxs[pr];
    const float tm = mask[q];

    {
        float rx = to_tf32(points[p*3+0] - points[q*3+0]);
        float ry = to_tf32(points[p*3+1] - points[q*3+1]);
        float rz = to_tf32(points[p*3+2] - points[q*3+2]);
        float4 v0 = {rx, ry, rz, 0.f};
        float4 z  = {0.f, 0.f, 0.f, 0.f};
        *(float4*)((char*)xbuf_all + wid*4096 + SMEM_SWZ128(lane*128 + 0))  = v0;
        *(float4*)((char*)xbuf_all + wid*4096 + SMEM_SWZ128(lane*128 + 16)) = z;
    }
    __syncwarp();

    const int a_row = lane & 15;
    const int a_hi  = (lane >> 4) * 16;

    float tmr[2][2];
    #pragma unroll
    for (int mi = 0; mi < 2; mi++) {
        tmr[mi][0] = __shfl_sync(0xffffffffu, tm, mi*16 + gg);
        tmr[mi][1] = __shfl_sync(0xffffffffu, tm, mi*16 + gg + 8);
    }

    // layer 1: 3(pad 8) -> 32
    float acc1[2][4][4];
    {
        uint32_t wf[4][2];
        float bv[4][2];
        #pragma unroll
        for (int nt = 0; nt < 4; nt++) {
            int n = nt * 8 + gg;
            wf[nt][0] = (kk < 3) ? __float_as_uint(to_tf32(w1[kk * H1 + n])) : 0u;
            wf[nt][1] = 0u;
            int c = nt * 8 + kk * 2;
            bv[nt][0] = b1[c]; bv[nt][1] = b1[c + 1];
        }
        uint32_t a[2][4];
        #pragma unroll
        for (int mi = 0; mi < 2; mi++) {
            uint32_t addr = xb + SMEM_SWZ128((mi*16 + a_row)*128 + a_hi);
            LDSM4(a[mi][0], a[mi][1], a[mi][2], a[mi][3], addr);
        }
        #pragma unroll
        for (int mi = 0; mi < 2; mi++)
            #pragma unroll
            for (int nt = 0; nt < 4; nt++) {
                acc1[mi][nt][0] = acc1[mi][nt][1] = acc1[mi][nt][2] = acc1[mi][nt][3] = 0.f;
                MMA_TF32(acc1[mi][nt], a[mi], wf[nt]);
                acc1[mi][nt][0] = to_tf32(fmaxf(acc1[mi][nt][0] + bv[nt][0], 0.f));
                acc1[mi][nt][1] = to_tf32(fmaxf(acc1[mi][nt][1] + bv[nt][1], 0.f));
                acc1[mi][nt][2] = to_tf32(fmaxf(acc1[mi][nt][2] + bv[nt][0], 0.f));
                acc1[mi][nt][3] = to_tf32(fmaxf(acc1[mi][nt][3] + bv[nt][1], 0.f));
            }
    }
    __syncwarp();
    #pragma unroll
    for (int mi = 0; mi < 2; mi++)
        #pragma unroll
        for (int nt = 0; nt < 4; nt++) {
            int c = nt * 8 + kk * 2;
            int r1 = mi*16 + gg, r2 = r1 + 8;
            *(float2*)((char*)xbuf_all + wid*4096 + SMEM_SWZ128(r1*128 + c*4)) =
                make_float2(acc1[mi][nt][0], acc1[mi][nt][1]);
            *(float2*)((char*)xbuf_all + wid*4096 + SMEM_SWZ128(r2*128 + c*4)) =
                make_float2(acc1[mi][nt][2], acc1[mi][nt][3]);
        }
    __syncwarp();

    // layer 2: 32 -> 32
    float acc2[2][4][4];
    {
        uint32_t wf[4][4][2];
        float bv[4][2];
        #pragma unroll
        for (int ks = 0; ks < 4; ks++)
            #pragma unroll
            for (int nt = 0; nt < 4; nt++) {
                int k = ks * 8 + kk, n = nt * 8 + gg;
                wf[ks][nt][0] = __float_as_uint(to_tf32(w2[k * H2 + n]));
                wf[ks][nt][1] = __float_as_uint(to_tf32(w2[(k + 4) * H2 + n]));
            }
        #pragma unroll
        for (int nt = 0; nt < 4; nt++) {
            int c = nt * 8 + kk * 2;
            bv[nt][0] = b2[c]; bv[nt][1] = b2[c + 1];
        }
        #pragma unroll
        for (int mi = 0; mi < 2; mi++)
            #pragma unroll
            for (int nt = 0; nt < 4; nt++)
                acc2[mi][nt][0] = acc2[mi][nt][1] = acc2[mi][nt][2] = acc2[mi][nt][3] = 0.f;
        #pragma unroll
        for (int ks = 0; ks < 4; ks++) {
            uint32_t a[2][4];
            #pragma unroll
            for (int mi = 0; mi < 2; mi++) {
                uint32_t addr = xb + SMEM_SWZ128((mi*16 + a_row)*128 + ks*32 + a_hi);
                LDSM4(a[mi][0], a[mi][1], a[mi][2], a[mi][3], addr);
            }
            #pragma unroll
            for (int mi = 0; mi < 2; mi++)
                #pragma unroll
                for (int nt = 0; nt < 4; nt++)
                    MMA_TF32(acc2[mi][nt], a[mi], wf[ks][nt]);
        }
        #pragma unroll
        for (int mi = 0; mi < 2; mi++)
            #pragma unroll
            for (int nt = 0; nt < 4; nt++) {
                acc2[mi][nt][0] = to_tf32(fmaxf(acc2[mi][nt][0] + bv[nt][0], 0.f));
                acc2[mi][nt][1] = to_tf32(fmaxf(acc2[mi][nt][1] + bv[nt][1], 0.f));
                acc2[mi][nt][2] = to_tf32(fmaxf(acc2[mi][nt][2] + bv[nt][0], 0.f));
                acc2[mi][nt][3] = to_tf32(fmaxf(acc2[mi][nt][3] + bv[nt][1], 0.f));
            }
    }
    __syncwarp();
    #pragma unroll
    for (int mi = 0; mi < 2; mi++)
        #pragma unroll
        for (int nt = 0; nt < 4; nt++) {
            int c = nt * 8 + kk * 2;
            int r1 = mi*16 + gg, r2 = r1 + 8;
            *(float2*)((char*)xbuf_all + wid*4096 + SMEM_SWZ128(r1*128 + c*4)) =
                make_float2(acc2[mi][nt][0], acc2[mi][nt][1]);
            *(float2*)((char*)xbuf_all + wid*4096 + SMEM_SWZ128(r2*128 + c*4)) =
                make_float2(acc2[mi][nt][2], acc2[mi][nt][3]);
        }
    __syncwarp();

    // layer 3: 32 -> 16, relu, * tmask
    {
        uint32_t wf[4][2][2];
        float bv[2][2];
        #pragma unroll
        for (int ks = 0; ks < 4; ks++)
            #pragma unroll
            for (int nt = 0; nt < 2; nt++) {
                int k = ks * 8 + kk, n = nt * 8 + gg;
                wf[ks][nt][0] = __float_as_uint(to_tf32(w3[k * CMID + n]));
                wf[ks][nt][1] = __float_as_uint(to_tf32(w3[(k + 4) * CMID + n]));
            }
        #pragma unroll
        for (int nt = 0; nt < 2; nt++) {
            int c = nt * 8 + kk * 2;
            bv[nt][0] = b3[c]; bv[nt][1] = b3[c + 1];
        }
        float acc3[2][2][4];
        #pragma unroll
        for (int mi = 0; mi < 2; mi++)
            #pragma unroll
            for (int nt = 0; nt < 2; nt++)
                acc3[mi][nt][0] = acc3[mi][nt][1] = acc3[mi][nt][2] = acc3[mi][nt][3] = 0.f;
        #pragma unroll
        for (int ks = 0; ks < 4; ks++) {
            uint32_t a[2][4];
            #pragma unroll
            for (int mi = 0; mi < 2; mi++) {
                uint32_t addr = xb + SMEM_SWZ128((mi*16 + a_row)*128 + ks*32 + a_hi);
                LDSM4(a[mi][0], a[mi][1], a[mi][2], a[mi][3], addr);
            }
            #pragma unroll
            for (int mi = 0; mi < 2; mi++)
                #pragma unroll
                for (int nt = 0; nt < 2; nt++)
                    MMA_TF32(acc3[mi][nt], a[mi], wf[ks][nt]);
        }
        const int r0w = blockIdx.x * 256 + wid * 32;
        #pragma unroll
        for (int mi = 0; mi < 2; mi++)
            #pragma unroll
            for (int nt = 0; nt < 2; nt++) {
                int c = nt * 8 + kk * 2;
                int r1 = r0w + mi*16 + gg, r2 = r1 + 8;
                float2 v1 = { fmaxf(acc3[mi][nt][0] + bv[nt][0], 0.f) * tmr[mi][0],
                              fmaxf(acc3[mi][nt][1] + bv[nt][1], 0.f) * tmr[mi][0] };
                float2 v2 = { fmaxf(acc3[mi][nt][2] + bv[nt][0], 0.f) * tmr[mi][1],
                              fmaxf(acc3[mi][nt][3] + bv[nt][1], 0.f) * tmr[mi][1] };
                *(float2*)(g_M + (size_t)r1 * CMID + c) = v1;
                *(float2*)(g_M + (size_t)r2 * CMID + c) = v2;
            }
    }
}

// ---------------------------------------------------------------------------
// Kernel 2b: einsum E[p][m*64+c] = sum_k m[p,k][m] * (feats[q]*tm)[c]
// ---------------------------------------------------------------------------
#define SFF_STRIDE 1032
#define SMM_STRIDE 260

__global__ void __launch_bounds__(128) k_eins(
    const float* __restrict__ feats, const float* __restrict__ mask)
{
    __shared__ float sff[8 * SFF_STRIDE];
    __shared__ float smm[8 * SMM_STRIDE];

    const int t  = threadIdx.x;
    const int pt = t >> 4;
    const int j  = t & 15;
    const int p  = blockIdx.x * 8 + pt;
    const int pr = p * KK + j;
    const int q  = (p / NN) * NN + g_idxs[pr];
    const float tm = mask[q];

    {
        const float4* fr = (const float4*)(feats + (size_t)q * CIN);
        float4* dst = (float4*)(sff + pt * SFF_STRIDE + j * CIN);
        #pragma unroll
        for (int c4 = 0; c4 < CIN / 4; c4++) {
            float4 v = fr[c4];
            v.x *= tm; v.y *= tm; v.z *= tm; v.w *= tm;
            dst[c4] = v;
        }
    }
    {
        const float4* mr = (const float4*)(g_M + (size_t)pr * CMID);
        float4* dst = (float4*)(smm + pt * SMM_STRIDE + j * CMID);
        #pragma unroll
        for (int c4 = 0; c4 < 4; c4++) dst[c4] = mr[c4];
    }
    __syncthreads();

    float acc[CMID][4];
    #pragma unroll
    for (int m2 = 0; m2 < CMID; m2++)
        acc[m2][0] = acc[m2][1] = acc[m2][2] = acc[m2][3] = 0.f;

    const float4* sfp = (const float4*)(sff + pt * SFF_STRIDE);
    const float4* smp = (const float4*)(smm + pt * SMM_STRIDE);
    #pragma unroll
    for (int k2 = 0; k2 < KK; k2++) {
        float4 f  = sfp[k2 * (CIN / 4) + j];
        float4 m0 = smp[k2 * 4 + 0];
        float4 m1 = smp[k2 * 4 + 1];
        float4 m2v = smp[k2 * 4 + 2];
        float4 m3 = smp[k2 * 4 + 3];
        const float mv[CMID] = {m0.x,m0.y,m0.z,m0.w, m1.x,m1.y,m1.z,m1.w,
                                m2v.x,m2v.y,m2v.z,m2v.w, m3.x,m3.y,m3.z,m3.w};
        #pragma unroll
        for (int m2 = 0; m2 < CMID; m2++) {
            acc[m2][0] += mv[m2] * f.x; acc[m2][1] += mv[m2] * f.y;
            acc[m2][2] += mv[m2] * f.z; acc[m2][3] += mv[m2] * f.w;
        }
    }
    float4* Ep = (float4*)(g_E + (size_t)p * EDIM);
    #pragma unroll
    for (int m2 = 0; m2 < CMID; m2++) {
        float4 v = {to_tf32(acc[m2][0]), to_tf32(acc[m2][1]),
                    to_tf32(acc[m2][2]), to_tf32(acc[m2][3])};
        Ep[m2 * (CIN / 4) + j] = v;
    }
}

// ---------------------------------------------------------------------------
// Kernel 3 (fused, mma.sync tf32) — R11 config (proven 172.1us):
//   H = relu(E @ f1 + fb1)  -> smem ;  out = H @ f2 + fb2
// CTA: 128 rows x N=256, 256 threads (8 warps), cp.async double buffer.
// ---------------------------------------------------------------------------
#define SA(s) ((s) * 49152)
#define SB(s) ((s) * 49152 + 16384)
#define HS_OFF 0
#define F2_OFF 131072
#define SMT 196608

__global__ void __launch_bounds__(256, 1) k_mma(
    const float* __restrict__ fb1, const float* __restrict__ fb2,
    float* __restrict__ out)
{
    extern __shared__ char sm[];
    const uint32_t sb = smem_u32(sm);
    const int t = threadIdx.x;
    const int lane = t & 31;
    const int wid  = t >> 5;
    const int row0 = blockIdx.x * 128;

    const int wm = wid >> 2;
    const int wn = wid & 3;

    const int a_row  = lane & 15;
    const int a_k16  = (lane >> 4) * 16;
    const int b_noff = (lane & 7) + ((lane & 16) >> 1);
    const int b_k16  = (lane & 8) * 2;

    float acc[4][8][4];
    #pragma unroll
    for (int i = 0; i < 4; i++)
        #pragma unroll
        for (int j = 0; j < 8; j++)
            acc[i][j][0] = acc[i][j][1] = acc[i][j][2] = acc[i][j][3] = 0.f;

    {
        #pragma unroll
        for (int s = 0; s < 4; s++) {
            int u = t + s * 256;  int r = u >> 3, c = u & 7;
            cpa16(sb + SA(0) + SMEM_SWZ128(r * 128 + c * 16),
                  g_E + (size_t)(row0 + r) * EDIM + c * 4);
        }
        #pragma unroll
        for (int s = 0; s < 8; s++) {
            int u = t + s * 256;  int n = u >> 3, c = u & 7;
            cpa16(sb + SB(0) + SMEM_SWZ128(n * 128 + c * 16),
                  g_f1T + (size_t)n * EDIM + c * 4);
        }
        CP_COMMIT();
    }

    for (int i = 0; i < 32; i++) {
        const int buf = i & 1;
        if (i < 31) {
            const int kc = (i + 1) * 32;
            const int nb = buf ^ 1;
            #pragma unroll
            for (int s = 0; s < 4; s++) {
                int u = t + s * 256;  int r = u >> 3, c = u & 7;
                cpa16(sb + SA(nb) + SMEM_SWZ128(r * 128 + c * 16),
                      g_E + (size_t)(row0 + r) * EDIM + kc + c * 4);
            }
            #pragma unroll
            for (int s = 0; s < 8; s++) {
                int u = t + s * 256;  int n = u >> 3, c = u & 7;
                cpa16(sb + SB(nb) + SMEM_SWZ128(n * 128 + c * 16),
                      g_f1T + (size_t)n * EDIM + kc + c * 4);
            }
            CP_COMMIT();
            CP_WAIT1();
        } else {
            CP_WAIT0();
        }
        __syncthreads();

        const uint32_t Ab = sb + SA(buf);
        const uint32_t Bb = sb + SB(buf);
        #pragma unroll
        for (int k8 = 0; k8 < 4; k8++) {
            uint32_t a[4][4];
            #pragma unroll
            for (int mi = 0; mi < 4; mi++) {
                uint32_t addr = Ab + SMEM_SWZ128(
                    (wm * 64 + mi * 16 + a_row) * 128 + k8 * 32 + a_k16);
                LDSM4(a[mi][0], a[mi][1], a[mi][2], a[mi][3], addr);
            }
            uint32_t bf[8][2];
            #pragma unroll
            for (int jj = 0; jj < 4; jj++) {
                uint32_t r0, r1, r2, r3;
                uint32_t addr = Bb + SMEM_SWZ128(
                    (wn * 64 + jj * 16 + b_noff) * 128 + k8 * 32 + b_k16);
                LDSM4(r0, r1, r2, r3, addr);
                bf[2*jj][0] = r0; bf[2*jj][1] = r1;
                bf[2*jj+1][0] = r2; bf[2*jj+1][1] = r3;
            }
            #pragma unroll
            for (int mi = 0; mi < 4; mi++)
                #pragma unroll
                for (int j = 0; j < 8; j++)
                    MMA_TF32(acc[mi][j], a[mi], bf[j]);
        }
        __syncthreads();
    }

    const int qrow = lane >> 2;
    const int qcol = (lane & 3) * 2;
    #pragma unroll
    for (int mi = 0; mi < 4; mi++) {
        #pragma unroll
        for (int j = 0; j < 8; j++) {
            const int col = wn * 64 + j * 8 + qcol;
            const float bv0 = __ldg(fb1 + col);
            const float bv1 = __ldg(fb1 + col + 1);
            const int r01 = wm * 64 + mi * 16 + qrow;
            const int r23 = r01 + 8;
            float2 h01 = { to_tf32(fmaxf(acc[mi][j][0] + bv0, 0.f)),
                           to_tf32(fmaxf(acc[mi][j][1] + bv1, 0.f)) };
            float2 h23 = { to_tf32(fmaxf(acc[mi][j][2] + bv0, 0.f)),
                           to_tf32(fmaxf(acc[mi][j][3] + bv1, 0.f)) };
            *(float2*)(sm + HS_OFF + swz2(r01, col >> 2) + (col & 3) * 4) = h01;
            *(float2*)(sm + HS_OFF + swz2(r23, col >> 2) + (col & 3) * 4) = h23;
        }
    }
    #pragma unroll
    for (int s = 0; s < 16; s++) {
        int u = t + s * 256;
        int n = u >> 6, c4 = u & 63;
        float4 v = *(const float4*)(g_f2T + (size_t)n * FH1 + c4 * 4);
        *(float4*)(sm + F2_OFF + swz2(n, c4)) = v;
    }
    __syncthreads();

    const int wm2 = wid >> 1;
    const int wn2 = wid & 1;
    float acc2[2][4][4];
    #pragma unroll
    for (int i = 0; i < 2; i++)
        #pragma unroll
        for (int j = 0; j < 4; j++)
            acc2[i][j][0] = acc2[i][j][1] = acc2[i][j][2] = acc2[i][j][3] = 0.f;

    #pragma unroll 4
    for (int k8 = 0; k8 < 32; k8++) {
        uint32_t a2[2][4];
        #pragma unroll
        for (int mi = 0; mi < 2; mi++) {
            uint32_t addr = sb + HS_OFF +
                swz2(wm2 * 32 + mi * 16 + a_row, k8 * 2 + (lane >> 4));
            LDSM4(a2[mi][0], a2[mi][1], a2[mi][2], a2[mi][3], addr);
        }
        uint32_t b2[4][2];
        #pragma unroll
        for (int jj = 0; jj < 2; jj++) {
            uint32_t r0, r1, r2, r3;
            uint32_t addr = sb + F2_OFF +
                swz2(wn2 * 32 + jj * 16 + b_noff, k8 * 2 + ((lane >> 3) & 1));
            LDSM4(r0, r1, r2, r3, addr);
            b2[2*jj][0] = r0; b2[2*jj][1] = r1;
            b2[2*jj+1][0] = r2; b2[2*jj+1][1] = r3;
        }
        #pragma unroll
        for (int mi = 0; mi < 2; mi++)
            #pragma unroll
            for (int j = 0; j < 4; j++)
                MMA_TF32(acc2[mi][j], a2[mi], b2[j]);
    }

    #pragma unroll
    for (int mi = 0; mi < 2; mi++) {
        #pragma unroll
        for (int j = 0; j < 4; j++) {
            const int col = wn2 * 32 + j * 8 + qcol;
            const float bv0 = __ldg(fb2 + col);
            const float bv1 = __ldg(fb2 + col + 1);
            const int row = row0 + wm2 * 32 + mi * 16 + qrow;
            float2 o01 = { acc2[mi][j][0] + bv0, acc2[mi][j][1] + bv1 };
            float2 o23 = { acc2[mi][j][2] + bv0, acc2[mi][j][3] + bv1 };
            *(float2*)(out + (size_t)row * COUT + col) = o01;
            *(float2*)(out + (size_t)(row + 8) * COUT + col) = o23;
        }
    }
}

// ---------------------------------------------------------------------------
extern "C" void kernel_launch(void* const* d_in, const int* in_sizes, int n_in,
                              void* d_out, int out_size) {
    const int*   groups = (const int*)  d_in[0];
    const float* points = (const float*)d_in[1];
    const float* feats  = (const float*)d_in[2];
    const float* pmask  = (const float*)d_in[3];
    const float* w1 = (const float*)d_in[4];
    const float* b1 = (const float*)d_in[5];
    const float* w2 = (const float*)d_in[6];
    const float* b2 = (const float*)d_in[7];
    const float* w3 = (const float*)d_in[8];
    const float* b3 = (const float*)d_in[9];
    const float* f1  = (const float*)d_in[10];
    const float* fb1 = (const float*)d_in[11];
    const float* f2  = (const float*)d_in[12];
    const float* fb2 = (const float*)d_in[13];
    float* out = (float*)d_out;

    cudaFuncSetAttribute(k_mma, cudaFuncAttributeMaxDynamicSharedMemorySize, SMT);

    k_prep<<<336, 256>>>(groups, f1, f2);
    k_mlp<<<NPAIR / 256, 256>>>(points, pmask, w1, b1, w2, b2, w3, b3);
    k_eins<<<NPTS / 8, 128>>>(feats, pmask);
    k_mma<<<NPTS / 128, 256, SMT>>>(fb1, fb2, out);
}

// round 16
// speedup vs baseline: 1.0220x; 1.0220x over previous
#include <cuda_runtime.h>
#include <cstdint>

#define BB 8
#define NN 2048
#define KK 16
#define CIN 64
#define CMID 16
#define COUT 64
#define H1 32
#define H2 32
#define FH1 256
#define NPTS (BB * NN)          // 16384
#define NPAIR (NPTS * KK)       // 262144
#define EDIM (CMID * CIN)       // 1024

// Scratch (device globals: no runtime allocation allowed)
__device__ int   g_idxs[NPAIR];
__device__ float g_E[(size_t)NPTS * EDIM];   // 64 MB (tf32-rounded)
__device__ float g_f1T[FH1 * EDIM];          // 1 MB  (f1^T [n][k], tf32)
__device__ float g_f2T[COUT * FH1];          // 64 KB (f2^T [n][k], tf32)

// ===========================================================================
// Helpers (base-ISA PTX only: mma.sync / ldmatrix / cp.async)
// ===========================================================================
__device__ __forceinline__ uint32_t smem_u32(const void* p) {
    uint32_t a;
    asm("{ .reg .u64 t; cvta.to.shared.u64 t, %1; cvt.u32.u64 %0, t; }"
        : "=r"(a) : "l"(p));
    return a;
}
__device__ __forceinline__ float to_tf32(float x) {
    uint32_t r;
    asm("cvt.rna.tf32.f32 %0, %1;" : "=r"(r) : "f"(x));
    return __uint_as_float(r);
}
__device__ __forceinline__ void cpa16(uint32_t dst, const float* src) {
    asm volatile("cp.async.cg.shared.global [%0], [%1], 16;"
                 :: "r"(dst), "l"(__cvta_generic_to_global(src)) : "memory");
}
#define CP_COMMIT() asm volatile("cp.async.commit_group;" ::: "memory")
#define CP_WAIT1()  asm volatile("cp.async.wait_group 1;" ::: "memory")
#define CP_WAIT0()  asm volatile("cp.async.wait_group 0;" ::: "memory")

#define SMEM_SWZ128(off) ((off) ^ (((off) >> 3) & 0x70))
// 1KB-row swizzle (rows of 256 floats = 64 chunks of 16B)
__device__ __forceinline__ uint32_t swz2(int row, int c) {
    return (uint32_t)(row * 1024 + ((c ^ (row & 7)) << 4));
}

#define LDSM4(r0, r1, r2, r3, addr) \
    asm volatile("ldmatrix.sync.aligned.m8n8.x4.shared.b16 {%0,%1,%2,%3}, [%4];" \
                 : "=r"(r0), "=r"(r1), "=r"(r2), "=r"(r3) : "r"(addr))

#define MMA_TF32(d, a, b) \
    asm volatile("mma.sync.aligned.m16n8k8.row.col.f32.tf32.tf32.f32 " \
                 "{%0,%1,%2,%3},{%4,%5,%6,%7},{%8,%9},{%0,%1,%2,%3};" \
                 : "+f"((d)[0]), "+f"((d)[1]), "+f"((d)[2]), "+f"((d)[3]) \
                 : "r"((a)[0]), "r"((a)[1]), "r"((a)[2]), "r"((a)[3]), \
                   "r"((b)[0]), "r"((b)[1]))

// ---------------------------------------------------------------------------
// Kernel 1 (merged prep): neighbor indices + f1/f2 transposes (tf32).
// Grid layout: blocks [0,64)   = idxs  (8 batches x 8 chunks of 256 points)
//              blocks [64,320) = f1 transpose (32 k-tiles x 8 n-tiles)
//              blocks [320,336)= f2 transpose (8 k-tiles x 2 n-tiles)
// ---------------------------------------------------------------------------
__global__ void __launch_bounds__(256) k_prep(
    const int* __restrict__ groups,
    const float* __restrict__ f1, const float* __restrict__ f2)
{
    __shared__ int   sg[NN];
    __shared__ float ts[32][33];
    const int bid = blockIdx.x;
    const int t   = threadIdx.x;

    if (bid < 64) {
        // --- neighbor indices (reference-stable order) ---
        const int b = bid >> 3;
        const int* gr = groups + (size_t)b * NN;
        for (int i = t; i < NN; i += 256) sg[i] = gr[i];
        __syncthreads();

        const int i = (bid & 7) * 256 + t;
        const int g = sg[i];
        const int base = (b * NN + i) * KK;
        int cnt = 0;
        for (int j = 0; j < NN; j++) {
            if (sg[j] == g) {
                g_idxs[base + cnt] = j;
                if (++cnt == KK) break;
            }
        }
        if (cnt < KK) {
            for (int j = 0; j < NN && cnt < KK; j++) {
                if (sg[j] != g) { g_idxs[base + cnt] = j; cnt++; }
            }
        }
    } else if (bid < 320) {
        // --- transpose f1 [1024][256] -> g_f1T [256][1024], tf32-rounded ---
        const int u = bid - 64;
        const int bx = u & 31;       // k-tile 0..31
        const int by = u >> 5;       // n-tile 0..7
        const int x = t & 31;
        const int y = t >> 5;        // 0..7
        #pragma unroll
        for (int s = 0; s < 4; s++) {
            int k = bx * 32 + y + s * 8;
            int n = by * 32 + x;
            ts[y + s * 8][x] = f1[(size_t)k * FH1 + n];
        }
        __syncthreads();
        #pragma unroll
        for (int s = 0; s < 4; s++) {
            int n = by * 32 + y + s * 8;
            int k = bx * 32 + x;
            g_f1T[(size_t)n * EDIM + k] = to_tf32(ts[x][y + s * 8]);
        }
    } else {
        // --- transpose f2 [256][64] -> g_f2T [64][256], tf32-rounded ---
        const int u = bid - 320;
        const int bx = u & 7;        // k-tile 0..7
        const int by = u >> 3;       // n-tile 0..1
        const int x = t & 31;
        const int y = t >> 5;
        #pragma unroll
        for (int s = 0; s < 4; s++) {
            int k = bx * 32 + y + s * 8;
            int n = by * 32 + x;
            ts[y + s * 8][x] = f2[(size_t)k * COUT + n];
        }
        __syncthreads();
        #pragma unroll
        for (int s = 0; s < 4; s++) {
            int n = by * 32 + y + s * 8;
            int k = bx * 32 + x;
            g_f2T[(size_t)n * FH1 + k] = to_tf32(ts[x][y + s * 8]);
        }
    }
}

// ---------------------------------------------------------------------------
// Kernel 2 (fused tensor-MLP + einsum): per block = 128 pairs = 8 points.
// Phase 1 (4 warps, warp-private): m = relu-MLP(rel) * tmask -> smm (smem)
// Phase 2: E[p][m*64+c] = sum_k m[p,k][m] * (feats[q]*tm)[c] -> g_E
// Shared pool: sff (8*1032 floats, 33KB) overlaps the per-warp xbuf region
// (4 warps x 4KB = 16KB) used only during phase 1.
// ---------------------------------------------------------------------------
#define SFF_STRIDE 1032
#define SMM_STRIDE 272

__global__ void __launch_bounds__(128) k_mlpe(
    const float* __restrict__ points, const float* __restrict__ feats,
    const float* __restrict__ mask,
    const float* __restrict__ w1, const float* __restrict__ b1,
    const float* __restrict__ w2, const float* __restrict__ b2,
    const float* __restrict__ w3, const float* __restrict__ b3)
{
    __shared__ float pool[8 * SFF_STRIDE];     // 33KB: xbuf (phase1) / sff (phase2)
    __shared__ float smm[8 * SMM_STRIDE];      // 8.7KB: masked m per point

    const int t    = threadIdx.x;
    const int lane = t & 31;
    const int wid  = t >> 5;                   // 0..3
    char* xbw = (char*)pool + wid * 4096;      // warp-private 4KB xbuf slice
    const uint32_t xb = smem_u32(xbw);

    const int kk = lane & 3;
    const int gg = lane >> 2;

    const int pr = blockIdx.x * 128 + wid * 32 + lane;
    const int p  = pr >> 4;
    const int q  = (p / NN) * NN + g_idxs[pr];
    const float tm = mask[q];

    {
        float rx = to_tf32(points[p*3+0] - points[q*3+0]);
        float ry = to_tf32(points[p*3+1] - points[q*3+1]);
        float rz = to_tf32(points[p*3+2] - points[q*3+2]);
        float4 v0 = {rx, ry, rz, 0.f};
        float4 z  = {0.f, 0.f, 0.f, 0.f};
        *(float4*)(xbw + SMEM_SWZ128(lane*128 + 0))  = v0;
        *(float4*)(xbw + SMEM_SWZ128(lane*128 + 16)) = z;
    }
    __syncwarp();

    const int a_row = lane & 15;
    const int a_hi  = (lane >> 4) * 16;

    float tmr[2][2];
    #pragma unroll
    for (int mi = 0; mi < 2; mi++) {
        tmr[mi][0] = __shfl_sync(0xffffffffu, tm, mi*16 + gg);
        tmr[mi][1] = __shfl_sync(0xffffffffu, tm, mi*16 + gg + 8);
    }

    // layer 1: 3(pad 8) -> 32
    float acc1[2][4][4];
    {
        uint32_t wf[4][2];
        float bv[4][2];
        #pragma unroll
        for (int nt = 0; nt < 4; nt++) {
            int n = nt * 8 + gg;
            wf[nt][0] = (kk < 3) ? __float_as_uint(to_tf32(w1[kk * H1 + n])) : 0u;
            wf[nt][1] = 0u;
            int c = nt * 8 + kk * 2;
            bv[nt][0] = b1[c]; bv[nt][1] = b1[c + 1];
        }
        uint32_t a[2][4];
        #pragma unroll
        for (int mi = 0; mi < 2; mi++) {
            uint32_t addr = xb + SMEM_SWZ128((mi*16 + a_row)*128 + a_hi);
            LDSM4(a[mi][0], a[mi][1], a[mi][2], a[mi][3], addr);
        }
        #pragma unroll
        for (int mi = 0; mi < 2; mi++)
            #pragma unroll
            for (int nt = 0; nt < 4; nt++) {
                acc1[mi][nt][0] = acc1[mi][nt][1] = acc1[mi][nt][2] = acc1[mi][nt][3] = 0.f;
                MMA_TF32(acc1[mi][nt], a[mi], wf[nt]);
                acc1[mi][nt][0] = to_tf32(fmaxf(acc1[mi][nt][0] + bv[nt][0], 0.f));
                acc1[mi][nt][1] = to_tf32(fmaxf(acc1[mi][nt][1] + bv[nt][1], 0.f));
                acc1[mi][nt][2] = to_tf32(fmaxf(acc1[mi][nt][2] + bv[nt][0], 0.f));
                acc1[mi][nt][3] = to_tf32(fmaxf(acc1[mi][nt][3] + bv[nt][1], 0.f));
            }
    }
    __syncwarp();
    #pragma unroll
    for (int mi = 0; mi < 2; mi++)
        #pragma unroll
        for (int nt = 0; nt < 4; nt++) {
            int c = nt * 8 + kk * 2;
            int r1 = mi*16 + gg, r2 = r1 + 8;
            *(float2*)(xbw + SMEM_SWZ128(r1*128 + c*4)) =
                make_float2(acc1[mi][nt][0], acc1[mi][nt][1]);
            *(float2*)(xbw + SMEM_SWZ128(r2*128 + c*4)) =
                make_float2(acc1[mi][nt][2], acc1[mi][nt][3]);
        }
    __syncwarp();

    // layer 2: 32 -> 32
    float acc2[2][4][4];
    {
        uint32_t wf[4][4][2];
        float bv[4][2];
        #pragma unroll
        for (int ks = 0; ks < 4; ks++)
            #pragma unroll
            for (int nt = 0; nt < 4; nt++) {
                int k = ks * 8 + kk, n = nt * 8 + gg;
                wf[ks][nt][0] = __float_as_uint(to_tf32(w2[k * H2 + n]));
                wf[ks][nt][1] = __float_as_uint(to_tf32(w2[(k + 4) * H2 + n]));
            }
        #pragma unroll
        for (int nt = 0; nt < 4; nt++) {
            int c = nt * 8 + kk * 2;
            bv[nt][0] = b2[c]; bv[nt][1] = b2[c + 1];
        }
        #pragma unroll
        for (int mi = 0; mi < 2; mi++)
            #pragma unroll
            for (int nt = 0; nt < 4; nt++)
                acc2[mi][nt][0] = acc2[mi][nt][1] = acc2[mi][nt][2] = acc2[mi][nt][3] = 0.f;
        #pragma unroll
        for (int ks = 0; ks < 4; ks++) {
            uint32_t a[2][4];
            #pragma unroll
            for (int mi = 0; mi < 2; mi++) {
                uint32_t addr = xb + SMEM_SWZ128((mi*16 + a_row)*128 + ks*32 + a_hi);
                LDSM4(a[mi][0], a[mi][1], a[mi][2], a[mi][3], addr);
            }
            #pragma unroll
            for (int mi = 0; mi < 2; mi++)
                #pragma unroll
                for (int nt = 0; nt < 4; nt++)
                    MMA_TF32(acc2[mi][nt], a[mi], wf[ks][nt]);
        }
        #pragma unroll
        for (int mi = 0; mi < 2; mi++)
            #pragma unroll
            for (int nt = 0; nt < 4; nt++) {
                acc2[mi][nt][0] = to_tf32(fmaxf(acc2[mi][nt][0] + bv[nt][0], 0.f));
                acc2[mi][nt][1] = to_tf32(fmaxf(acc2[mi][nt][1] + bv[nt][1], 0.f));
                acc2[mi][nt][2] = to_tf32(fmaxf(acc2[mi][nt][2] + bv[nt][0], 0.f));
                acc2[mi][nt][3] = to_tf32(fmaxf(acc2[mi][nt][3] + bv[nt][1], 0.f));
            }
    }
    __syncwarp();
    #pragma unroll
    for (int mi = 0; mi < 2; mi++)
        #pragma unroll
        for (int nt = 0; nt < 4; nt++) {
            int c = nt * 8 + kk * 2;
            int r1 = mi*16 + gg, r2 = r1 + 8;
            *(float2*)(xbw + SMEM_SWZ128(r1*128 + c*4)) =
                make_float2(acc2[mi][nt][0], acc2[mi][nt][1]);
            *(float2*)(xbw + SMEM_SWZ128(r2*128 + c*4)) =
                make_float2(acc2[mi][nt][2], acc2[mi][nt][3]);
        }
    __syncwarp();

    // layer 3: 32 -> 16, relu, * tmask  -> smm (smem, not global)
    {
        uint32_t wf[4][2][2];
        float bv[2][2];
        #pragma unroll
        for (int ks = 0; ks < 4; ks++)
            #pragma unroll
            for (int nt = 0; nt < 2; nt++) {
                int k = ks * 8 + kk, n = nt * 8 + gg;
                wf[ks][nt][0] = __float_as_uint(to_tf32(w3[k * CMID + n]));
                wf[ks][nt][1] = __float_as_uint(to_tf32(w3[(k + 4) * CMID + n]));
            }
        #pragma unroll
        for (int nt = 0; nt < 2; nt++) {
            int c = nt * 8 + kk * 2;
            bv[nt][0] = b3[c]; bv[nt][1] = b3[c + 1];
        }
        float acc3[2][2][4];
        #pragma unroll
        for (int mi = 0; mi < 2; mi++)
            #pragma unroll
            for (int nt = 0; nt < 2; nt++)
                acc3[mi][nt][0] = acc3[mi][nt][1] = acc3[mi][nt][2] = acc3[mi][nt][3] = 0.f;
        #pragma unroll
        for (int ks = 0; ks < 4; ks++) {
            uint32_t a[2][4];
            #pragma unroll
            for (int mi = 0; mi < 2; mi++) {
                uint32_t addr = xb + SMEM_SWZ128((mi*16 + a_row)*128 + ks*32 + a_hi);
                LDSM4(a[mi][0], a[mi][1], a[mi][2], a[mi][3], addr);
            }
            #pragma unroll
            for (int mi = 0; mi < 2; mi++)
                #pragma unroll
                for (int nt = 0; nt < 2; nt++)
                    MMA_TF32(acc3[mi][nt], a[mi], wf[ks][nt]);
        }
        const int r0l = wid * 32;   // local pair base within block
        #pragma unroll
        for (int mi = 0; mi < 2; mi++)
            #pragma unroll
            for (int nt = 0; nt < 2; nt++) {
                int c = nt * 8 + kk * 2;
                int r1 = r0l + mi*16 + gg, r2 = r1 + 8;
                float2 v1 = { fmaxf(acc3[mi][nt][0] + bv[nt][0], 0.f) * tmr[mi][0],
                              fmaxf(acc3[mi][nt][1] + bv[nt][1], 0.f) * tmr[mi][0] };
                float2 v2 = { fmaxf(acc3[mi][nt][2] + bv[nt][0], 0.f) * tmr[mi][1],
                              fmaxf(acc3[mi][nt][3] + bv[nt][1], 0.f) * tmr[mi][1] };
                *(float2*)(smm + (r1 >> 4) * SMM_STRIDE + (r1 & 15) * CMID + c) = v1;
                *(float2*)(smm + (r2 >> 4) * SMM_STRIDE + (r2 & 15) * CMID + c) = v2;
            }
    }
    __syncthreads();   // all warps done with xbuf + smm populated

    // ---- phase 2: einsum (k_eins body; sff overlaps dead xbuf region) ----
    {
        const int pt = t >> 4;           // point slot 0..7
        const int j  = t & 15;           // neighbor / c-quad slot
        const int p2  = blockIdx.x * 8 + pt;
        const int pr2 = p2 * KK + j;
        const int q2  = (p2 / NN) * NN + g_idxs[pr2];
        const float tm2 = mask[q2];

        {
            const float4* fr = (const float4*)(feats + (size_t)q2 * CIN);
            float4* dst = (float4*)(pool + pt * SFF_STRIDE + j * CIN);
            #pragma unroll
            for (int c4 = 0; c4 < CIN / 4; c4++) {
                float4 v = fr[c4];
                v.x *= tm2; v.y *= tm2; v.z *= tm2; v.w *= tm2;
                dst[c4] = v;
            }
        }
        __syncthreads();

        float acc[CMID][4];
        #pragma unroll
        for (int m2 = 0; m2 < CMID; m2++)
            acc[m2][0] = acc[m2][1] = acc[m2][2] = acc[m2][3] = 0.f;

        const float4* sfp = (const float4*)(pool + pt * SFF_STRIDE);
        const float4* smp = (const float4*)(smm + pt * SMM_STRIDE);
        #pragma unroll
        for (int k2 = 0; k2 < KK; k2++) {
            float4 f  = sfp[k2 * (CIN / 4) + j];
            float4 m0 = smp[k2 * 4 + 0];
            float4 m1 = smp[k2 * 4 + 1];
            float4 m2v = smp[k2 * 4 + 2];
            float4 m3 = smp[k2 * 4 + 3];
            const float mv[CMID] = {m0.x,m0.y,m0.z,m0.w, m1.x,m1.y,m1.z,m1.w,
                                    m2v.x,m2v.y,m2v.z,m2v.w, m3.x,m3.y,m3.z,m3.w};
            #pragma unroll
            for (int m2 = 0; m2 < CMID; m2++) {
                acc[m2][0] += mv[m2] * f.x; acc[m2][1] += mv[m2] * f.y;
                acc[m2][2] += mv[m2] * f.z; acc[m2][3] += mv[m2] * f.w;
            }
        }
        float4* Ep = (float4*)(g_E + (size_t)p2 * EDIM);
        #pragma unroll
        for (int m2 = 0; m2 < CMID; m2++) {
            float4 v = {to_tf32(acc[m2][0]), to_tf32(acc[m2][1]),
                        to_tf32(acc[m2][2]), to_tf32(acc[m2][3])};
            Ep[m2 * (CIN / 4) + j] = v;
        }
    }
}

// ---------------------------------------------------------------------------
// Kernel 3 (fused, mma.sync tf32) — R11 config (proven 172.1us):
//   H = relu(E @ f1 + fb1)  -> smem ;  out = H @ f2 + fb2
// CTA: 128 rows x N=256, 256 threads (8 warps), cp.async double buffer.
// ---------------------------------------------------------------------------
#define SA(s) ((s) * 49152)
#define SB(s) ((s) * 49152 + 16384)
#define HS_OFF 0
#define F2_OFF 131072
#define SMT 196608

__global__ void __launch_bounds__(256, 1) k_mma(
    const float* __restrict__ fb1, const float* __restrict__ fb2,
    float* __restrict__ out)
{
    extern __shared__ char sm[];
    const uint32_t sb = smem_u32(sm);
    const int t = threadIdx.x;
    const int lane = t & 31;
    const int wid  = t >> 5;
    const int row0 = blockIdx.x * 128;

    const int wm = wid >> 2;
    const int wn = wid & 3;

    const int a_row  = lane & 15;
    const int a_k16  = (lane >> 4) * 16;
    const int b_noff = (lane & 7) + ((lane & 16) >> 1);
    const int b_k16  = (lane & 8) * 2;

    float acc[4][8][4];
    #pragma unroll
    for (int i = 0; i < 4; i++)
        #pragma unroll
        for (int j = 0; j < 8; j++)
            acc[i][j][0] = acc[i][j][1] = acc[i][j][2] = acc[i][j][3] = 0.f;

    {
        #pragma unroll
        for (int s = 0; s < 4; s++) {
            int u = t + s * 256;  int r = u >> 3, c = u & 7;
            cpa16(sb + SA(0) + SMEM_SWZ128(r * 128 + c * 16),
                  g_E + (size_t)(row0 + r) * EDIM + c * 4);
        }
        #pragma unroll
        for (int s = 0; s < 8; s++) {
            int u = t + s * 256;  int n = u >> 3, c = u & 7;
            cpa16(sb + SB(0) + SMEM_SWZ128(n * 128 + c * 16),
                  g_f1T + (size_t)n * EDIM + c * 4);
        }
        CP_COMMIT();
    }

    for (int i = 0; i < 32; i++) {
        const int buf = i & 1;
        if (i < 31) {
            const int kc = (i + 1) * 32;
            const int nb = buf ^ 1;
            #pragma unroll
            for (int s = 0; s < 4; s++) {
                int u = t + s * 256;  int r = u >> 3, c = u & 7;
                cpa16(sb + SA(nb) + SMEM_SWZ128(r * 128 + c * 16),
                      g_E + (size_t)(row0 + r) * EDIM + kc + c * 4);
            }
            #pragma unroll
            for (int s = 0; s < 8; s++) {
                int u = t + s * 256;  int n = u >> 3, c = u & 7;
                cpa16(sb + SB(nb) + SMEM_SWZ128(n * 128 + c * 16),
                      g_f1T + (size_t)n * EDIM + kc + c * 4);
            }
            CP_COMMIT();
            CP_WAIT1();
        } else {
            CP_WAIT0();
        }
        __syncthreads();

        const uint32_t Ab = sb + SA(buf);
        const uint32_t Bb = sb + SB(buf);
        #pragma unroll
        for (int k8 = 0; k8 < 4; k8++) {
            uint32_t a[4][4];
            #pragma unroll
            for (int mi = 0; mi < 4; mi++) {
                uint32_t addr = Ab + SMEM_SWZ128(
                    (wm * 64 + mi * 16 + a_row) * 128 + k8 * 32 + a_k16);
                LDSM4(a[mi][0], a[mi][1], a[mi][2], a[mi][3], addr);
            }
            uint32_t bf[8][2];
            #pragma unroll
            for (int jj = 0; jj < 4; jj++) {
                uint32_t r0, r1, r2, r3;
                uint32_t addr = Bb + SMEM_SWZ128(
                    (wn * 64 + jj * 16 + b_noff) * 128 + k8 * 32 + b_k16);
                LDSM4(r0, r1, r2, r3, addr);
                bf[2*jj][0] = r0; bf[2*jj][1] = r1;
                bf[2*jj+1][0] = r2; bf[2*jj+1][1] = r3;
            }
            #pragma unroll
            for (int mi = 0; mi < 4; mi++)
                #pragma unroll
                for (int j = 0; j < 8; j++)
                    MMA_TF32(acc[mi][j], a[mi], bf[j]);
        }
        __syncthreads();
    }

    const int qrow = lane >> 2;
    const int qcol = (lane & 3) * 2;
    #pragma unroll
    for (int mi = 0; mi < 4; mi++) {
        #pragma unroll
        for (int j = 0; j < 8; j++) {
            const int col = wn * 64 + j * 8 + qcol;
            const float bv0 = __ldg(fb1 + col);
            const float bv1 = __ldg(fb1 + col + 1);
            const int r01 = wm * 64 + mi * 16 + qrow;
            const int r23 = r01 + 8;
            float2 h01 = { to_tf32(fmaxf(acc[mi][j][0] + bv0, 0.f)),
                           to_tf32(fmaxf(acc[mi][j][1] + bv1, 0.f)) };
            float2 h23 = { to_tf32(fmaxf(acc[mi][j][2] + bv0, 0.f)),
                           to_tf32(fmaxf(acc[mi][j][3] + bv1, 0.f)) };
            *(float2*)(sm + HS_OFF + swz2(r01, col >> 2) + (col & 3) * 4) = h01;
            *(float2*)(sm + HS_OFF + swz2(r23, col >> 2) + (col & 3) * 4) = h23;
        }
    }
    #pragma unroll
    for (int s = 0; s < 16; s++) {
        int u = t + s * 256;
        int n = u >> 6, c4 = u & 63;
        float4 v = *(const float4*)(g_f2T + (size_t)n * FH1 + c4 * 4);
        *(float4*)(sm + F2_OFF + swz2(n, c4)) = v;
    }
    __syncthreads();

    const int wm2 = wid >> 1;
    const int wn2 = wid & 1;
    float acc2[2][4][4];
    #pragma unroll
    for (int i = 0; i < 2; i++)
        #pragma unroll
        for (int j = 0; j < 4; j++)
            acc2[i][j][0] = acc2[i][j][1] = acc2[i][j][2] = acc2[i][j][3] = 0.f;

    #pragma unroll 4
    for (int k8 = 0; k8 < 32; k8++) {
        uint32_t a2[2][4];
        #pragma unroll
        for (int mi = 0; mi < 2; mi++) {
            uint32_t addr = sb + HS_OFF +
                swz2(wm2 * 32 + mi * 16 + a_row, k8 * 2 + (lane >> 4));
            LDSM4(a2[mi][0], a2[mi][1], a2[mi][2], a2[mi][3], addr);
        }
        uint32_t b2[4][2];
        #pragma unroll
        for (int jj = 0; jj < 2; jj++) {
            uint32_t r0, r1, r2, r3;
            uint32_t addr = sb + F2_OFF +
                swz2(wn2 * 32 + jj * 16 + b_noff, k8 * 2 + ((lane >> 3) & 1));
            LDSM4(r0, r1, r2, r3, addr);
            b2[2*jj][0] = r0; b2[2*jj][1] = r1;
            b2[2*jj+1][0] = r2; b2[2*jj+1][1] = r3;
        }
        #pragma unroll
        for (int mi = 0; mi < 2; mi++)
            #pragma unroll
            for (int j = 0; j < 4; j++)
                MMA_TF32(acc2[mi][j], a2[mi], b2[j]);
    }

    #pragma unroll
    for (int mi = 0; mi < 2; mi++) {
        #pragma unroll
        for (int j = 0; j < 4; j++) {
            const int col = wn2 * 32 + j * 8 + qcol;
            const float bv0 = __ldg(fb2 + col);
            const float bv1 = __ldg(fb2 + col + 1);
            const int row = row0 + wm2 * 32 + mi * 16 + qrow;
            float2 o01 = { acc2[mi][j][0] + bv0, acc2[mi][j][1] + bv1 };
            float2 o23 = { acc2[mi][j][2] + bv0, acc2[mi][j][3] + bv1 };
            *(float2*)(out + (size_t)row * COUT + col) = o01;
            *(float2*)(out + (size_t)(row + 8) * COUT + col) = o23;
        }
    }
}

// ---------------------------------------------------------------------------
extern "C" void kernel_launch(void* const* d_in, const int* in_sizes, int n_in,
                              void* d_out, int out_size) {
    const int*   groups = (const int*)  d_in[0];
    const float* points = (const float*)d_in[1];
    const float* feats  = (const float*)d_in[2];
    const float* pmask  = (const float*)d_in[3];
    const float* w1 = (const float*)d_in[4];
    const float* b1 = (const float*)d_in[5];
    const float* w2 = (const float*)d_in[6];
    const float* b2 = (const float*)d_in[7];
    const float* w3 = (const float*)d_in[8];
    const float* b3 = (const float*)d_in[9];
    const float* f1  = (const float*)d_in[10];
    const float* fb1 = (const float*)d_in[11];
    const float* f2  = (const float*)d_in[12];
    const float* fb2 = (const float*)d_in[13];
    float* out = (float*)d_out;

    cudaFuncSetAttribute(k_mma, cudaFuncAttributeMaxDynamicSharedMemorySize, SMT);

    k_prep<<<336, 256>>>(groups, f1, f2);
    k_mlpe<<<NPAIR / 128, 128>>>(points, feats, pmask,
                                 w1, b1, w2, b2, w3, b3);
    k_mma<<<NPTS / 128, 256, SMT>>>(fb1, fb2, out);
}

// round 17
// speedup vs baseline: 1.0591x; 1.0362x over previous
#include <cuda_runtime.h>
#include <cstdint>

#define BB 8
#define NN 2048
#define KK 16
#define CIN 64
#define CMID 16
#define COUT 64
#define H1 32
#define H2 32
#define FH1 256
#define NPTS (BB * NN)          // 16384
#define NPAIR (NPTS * KK)       // 262144
#define EDIM (CMID * CIN)       // 1024

// Scratch (device globals: no runtime allocation allowed)
__device__ int   g_idxs[NPAIR];
__device__ float g_E[(size_t)NPTS * EDIM];   // 64 MB (tf32-rounded)
__device__ float g_f1T[FH1 * EDIM];          // 1 MB  (f1^T [n][k], tf32)
__device__ float g_f2T[COUT * FH1];          // 64 KB (f2^T [n][k], tf32)

// ===========================================================================
// Helpers (base-ISA PTX only: mma.sync / ldmatrix / cp.async)
// ===========================================================================
__device__ __forceinline__ uint32_t smem_u32(const void* p) {
    uint32_t a;
    asm("{ .reg .u64 t; cvta.to.shared.u64 t, %1; cvt.u32.u64 %0, t; }"
        : "=r"(a) : "l"(p));
    return a;
}
__device__ __forceinline__ float to_tf32(float x) {
    uint32_t r;
    asm("cvt.rna.tf32.f32 %0, %1;" : "=r"(r) : "f"(x));
    return __uint_as_float(r);
}
__device__ __forceinline__ void cpa16(uint32_t dst, const float* src) {
    asm volatile("cp.async.cg.shared.global [%0], [%1], 16;"
                 :: "r"(dst), "l"(__cvta_generic_to_global(src)) : "memory");
}
#define CP_COMMIT() asm volatile("cp.async.commit_group;" ::: "memory")
#define CP_WAIT1()  asm volatile("cp.async.wait_group 1;" ::: "memory")
#define CP_WAIT0()  asm volatile("cp.async.wait_group 0;" ::: "memory")

#define SMEM_SWZ128(off) ((off) ^ (((off) >> 3) & 0x70))
// 1KB-row swizzle (rows of 256 floats = 64 chunks of 16B)
__device__ __forceinline__ uint32_t swz2(int row, int c) {
    return (uint32_t)(row * 1024 + ((c ^ (row & 7)) << 4));
}

#define LDSM4(r0, r1, r2, r3, addr) \
    asm volatile("ldmatrix.sync.aligned.m8n8.x4.shared.b16 {%0,%1,%2,%3}, [%4];" \
                 : "=r"(r0), "=r"(r1), "=r"(r2), "=r"(r3) : "r"(addr))

#define MMA_TF32(d, a, b) \
    asm volatile("mma.sync.aligned.m16n8k8.row.col.f32.tf32.tf32.f32 " \
                 "{%0,%1,%2,%3},{%4,%5,%6,%7},{%8,%9},{%0,%1,%2,%3};" \
                 : "+f"((d)[0]), "+f"((d)[1]), "+f"((d)[2]), "+f"((d)[3]) \
                 : "r"((a)[0]), "r"((a)[1]), "r"((a)[2]), "r"((a)[3]), \
                   "r"((b)[0]), "r"((b)[1]))

// ---------------------------------------------------------------------------
// Kernel 1 (merged prep): neighbor indices (warp-ballot) + f1/f2 transposes.
// Grid layout: blocks [0,256)   = idxs  (8 batches x 32 chunks of 64 points;
//                                        1 warp per point, ballot scan)
//              blocks [256,512) = f1 transpose (32 k-tiles x 8 n-tiles)
//              blocks [512,528) = f2 transpose (8 k-tiles x 2 n-tiles)
// ---------------------------------------------------------------------------
__global__ void __launch_bounds__(256) k_prep(
    const int* __restrict__ groups,
    const float* __restrict__ f1, const float* __restrict__ f2)
{
    __shared__ int   sg[NN];
    __shared__ float ts[32][33];
    const int bid = blockIdx.x;
    const int t   = threadIdx.x;

    if (bid < 256) {
        // --- neighbor indices: 1 warp per point, ballot-ranked scan ---
        const int b     = bid >> 5;            // batch
        const int pbase = (bid & 31) * 64;     // first point (within batch)
        const int lane  = t & 31;
        const int w     = t >> 5;              // warp 0..7
        const int* gr = groups + (size_t)b * NN;
        for (int i = t; i < NN; i += 256) sg[i] = gr[i];
        __syncthreads();

        const uint32_t lmask = (1u << lane) - 1u;
        #pragma unroll
        for (int pp = 0; pp < 8; pp++) {
            const int il = pbase + w * 8 + pp;          // point index in batch
            const int g  = sg[il];
            const int base = (b * NN + il) * KK;
            int cnt = 0;
            // phase 1: matching j in increasing order
            for (int j0 = 0; j0 < NN && cnt < KK; j0 += 32) {
                const int j = j0 + lane;
                const bool m = (sg[j] == g);
                const uint32_t mk = __ballot_sync(0xffffffffu, m);
                const int pos = cnt + __popc(mk & lmask);
                if (m && pos < KK) g_idxs[base + pos] = j;
                cnt += __popc(mk);
            }
            // phase 2: if short, non-matching j in increasing order
            if (cnt < KK) {
                int c2 = cnt;
                for (int j0 = 0; j0 < NN && c2 < KK; j0 += 32) {
                    const int j = j0 + lane;
                    const bool m = (sg[j] != g);
                    const uint32_t mk = __ballot_sync(0xffffffffu, m);
                    const int pos = c2 + __popc(mk & lmask);
                    if (m && pos < KK) g_idxs[base + pos] = j;
                    c2 += __popc(mk);
                }
            }
        }
    } else if (bid < 512) {
        // --- transpose f1 [1024][256] -> g_f1T [256][1024], tf32-rounded ---
        const int u = bid - 256;
        const int bx = u & 31;       // k-tile 0..31
        const int by = u >> 5;       // n-tile 0..7
        const int x = t & 31;
        const int y = t >> 5;        // 0..7
        #pragma unroll
        for (int s = 0; s < 4; s++) {
            int k = bx * 32 + y + s * 8;
            int n = by * 32 + x;
            ts[y + s * 8][x] = f1[(size_t)k * FH1 + n];
        }
        __syncthreads();
        #pragma unroll
        for (int s = 0; s < 4; s++) {
            int n = by * 32 + y + s * 8;
            int k = bx * 32 + x;
            g_f1T[(size_t)n * EDIM + k] = to_tf32(ts[x][y + s * 8]);
        }
    } else {
        // --- transpose f2 [256][64] -> g_f2T [64][256], tf32-rounded ---
        const int u = bid - 512;
        const int bx = u & 7;        // k-tile 0..7
        const int by = u >> 3;       // n-tile 0..1
        const int x = t & 31;
        const int y = t >> 5;
        #pragma unroll
        for (int s = 0; s < 4; s++) {
            int k = bx * 32 + y + s * 8;
            int n = by * 32 + x;
            ts[y + s * 8][x] = f2[(size_t)k * COUT + n];
        }
        __syncthreads();
        #pragma unroll
        for (int s = 0; s < 4; s++) {
            int n = by * 32 + y + s * 8;
            int k = bx * 32 + x;
            g_f2T[(size_t)n * FH1 + k] = to_tf32(ts[x][y + s * 8]);
        }
    }
}

// ---------------------------------------------------------------------------
// Kernel 2 (fused tensor-MLP + einsum): per block = 128 pairs = 8 points.
// Phase 1 (4 warps, warp-private): m = relu-MLP(rel) * tmask -> smm (smem)
// Phase 2: E[p][m*64+c] = sum_k m[p,k][m] * (feats[q]*tm)[c] -> g_E
// ---------------------------------------------------------------------------
#define SFF_STRIDE 1032
#define SMM_STRIDE 272

__global__ void __launch_bounds__(128) k_mlpe(
    const float* __restrict__ points, const float* __restrict__ feats,
    const float* __restrict__ mask,
    const float* __restrict__ w1, const float* __restrict__ b1,
    const float* __restrict__ w2, const float* __restrict__ b2,
    const float* __restrict__ w3, const float* __restrict__ b3)
{
    __shared__ float pool[8 * SFF_STRIDE];     // 33KB: xbuf (phase1) / sff (phase2)
    __shared__ float smm[8 * SMM_STRIDE];      // 8.7KB: masked m per point

    const int t    = threadIdx.x;
    const int lane = t & 31;
    const int wid  = t >> 5;                   // 0..3
    char* xbw = (char*)pool + wid * 4096;      // warp-private 4KB xbuf slice
    const uint32_t xb = smem_u32(xbw);

    const int kk = lane & 3;
    const int gg = lane >> 2;

    const int pr = blockIdx.x * 128 + wid * 32 + lane;
    const int p  = pr >> 4;
    const int q  = (p / NN) * NN + g_idxs[pr];
    const float tm = mask[q];

    {
        float rx = to_tf32(points[p*3+0] - points[q*3+0]);
        float ry = to_tf32(points[p*3+1] - points[q*3+1]);
        float rz = to_tf32(points[p*3+2] - points[q*3+2]);
        float4 v0 = {rx, ry, rz, 0.f};
        float4 z  = {0.f, 0.f, 0.f, 0.f};
        *(float4*)(xbw + SMEM_SWZ128(lane*128 + 0))  = v0;
        *(float4*)(xbw + SMEM_SWZ128(lane*128 + 16)) = z;
    }
    __syncwarp();

    const int a_row = lane & 15;
    const int a_hi  = (lane >> 4) * 16;

    float tmr[2][2];
    #pragma unroll
    for (int mi = 0; mi < 2; mi++) {
        tmr[mi][0] = __shfl_sync(0xffffffffu, tm, mi*16 + gg);
        tmr[mi][1] = __shfl_sync(0xffffffffu, tm, mi*16 + gg + 8);
    }

    // layer 1: 3(pad 8) -> 32
    float acc1[2][4][4];
    {
        uint32_t wf[4][2];
        float bv[4][2];
        #pragma unroll
        for (int nt = 0; nt < 4; nt++) {
            int n = nt * 8 + gg;
            wf[nt][0] = (kk < 3) ? __float_as_uint(to_tf32(w1[kk * H1 + n])) : 0u;
            wf[nt][1] = 0u;
            int c = nt * 8 + kk * 2;
            bv[nt][0] = b1[c]; bv[nt][1] = b1[c + 1];
        }
        uint32_t a[2][4];
        #pragma unroll
        for (int mi = 0; mi < 2; mi++) {
            uint32_t addr = xb + SMEM_SWZ128((mi*16 + a_row)*128 + a_hi);
            LDSM4(a[mi][0], a[mi][1], a[mi][2], a[mi][3], addr);
        }
        #pragma unroll
        for (int mi = 0; mi < 2; mi++)
            #pragma unroll
            for (int nt = 0; nt < 4; nt++) {
                acc1[mi][nt][0] = acc1[mi][nt][1] = acc1[mi][nt][2] = acc1[mi][nt][3] = 0.f;
                MMA_TF32(acc1[mi][nt], a[mi], wf[nt]);
                acc1[mi][nt][0] = to_tf32(fmaxf(acc1[mi][nt][0] + bv[nt][0], 0.f));
                acc1[mi][nt][1] = to_tf32(fmaxf(acc1[mi][nt][1] + bv[nt][1], 0.f));
                acc1[mi][nt][2] = to_tf32(fmaxf(acc1[mi][nt][2] + bv[nt][0], 0.f));
                acc1[mi][nt][3] = to_tf32(fmaxf(acc1[mi][nt][3] + bv[nt][1], 0.f));
            }
    }
    __syncwarp();
    #pragma unroll
    for (int mi = 0; mi < 2; mi++)
        #pragma unroll
        for (int nt = 0; nt < 4; nt++) {
            int c = nt * 8 + kk * 2;
            int r1 = mi*16 + gg, r2 = r1 + 8;
            *(float2*)(xbw + SMEM_SWZ128(r1*128 + c*4)) =
                make_float2(acc1[mi][nt][0], acc1[mi][nt][1]);
            *(float2*)(xbw + SMEM_SWZ128(r2*128 + c*4)) =
                make_float2(acc1[mi][nt][2], acc1[mi][nt][3]);
        }
    __syncwarp();

    // layer 2: 32 -> 32
    float acc2[2][4][4];
    {
        uint32_t wf[4][4][2];
        float bv[4][2];
        #pragma unroll
        for (int ks = 0; ks < 4; ks++)
            #pragma unroll
            for (int nt = 0; nt < 4; nt++) {
                int k = ks * 8 + kk, n = nt * 8 + gg;
                wf[ks][nt][0] = __float_as_uint(to_tf32(w2[k * H2 + n]));
                wf[ks][nt][1] = __float_as_uint(to_tf32(w2[(k + 4) * H2 + n]));
            }
        #pragma unroll
        for (int nt = 0; nt < 4; nt++) {
            int c = nt * 8 + kk * 2;
            bv[nt][0] = b2[c]; bv[nt][1] = b2[c + 1];
        }
        #pragma unroll
        for (int mi = 0; mi < 2; mi++)
            #pragma unroll
            for (int nt = 0; nt < 4; nt++)
                acc2[mi][nt][0] = acc2[mi][nt][1] = acc2[mi][nt][2] = acc2[mi][nt][3] = 0.f;
        #pragma unroll
        for (int ks = 0; ks < 4; ks++) {
            uint32_t a[2][4];
            #pragma unroll
            for (int mi = 0; mi < 2; mi++) {
                uint32_t addr = xb + SMEM_SWZ128((mi*16 + a_row)*128 + ks*32 + a_hi);
                LDSM4(a[mi][0], a[mi][1], a[mi][2], a[mi][3], addr);
            }
            #pragma unroll
            for (int mi = 0; mi < 2; mi++)
                #pragma unroll
                for (int nt = 0; nt < 4; nt++)
                    MMA_TF32(acc2[mi][nt], a[mi], wf[ks][nt]);
        }
        #pragma unroll
        for (int mi = 0; mi < 2; mi++)
            #pragma unroll
            for (int nt = 0; nt < 4; nt++) {
                acc2[mi][nt][0] = to_tf32(fmaxf(acc2[mi][nt][0] + bv[nt][0], 0.f));
                acc2[mi][nt][1] = to_tf32(fmaxf(acc2[mi][nt][1] + bv[nt][1], 0.f));
                acc2[mi][nt][2] = to_tf32(fmaxf(acc2[mi][nt][2] + bv[nt][0], 0.f));
                acc2[mi][nt][3] = to_tf32(fmaxf(acc2[mi][nt][3] + bv[nt][1], 0.f));
            }
    }
    __syncwarp();
    #pragma unroll
    for (int mi = 0; mi < 2; mi++)
        #pragma unroll
        for (int nt = 0; nt < 4; nt++) {
            int c = nt * 8 + kk * 2;
            int r1 = mi*16 + gg, r2 = r1 + 8;
            *(float2*)(xbw + SMEM_SWZ128(r1*128 + c*4)) =
                make_float2(acc2[mi][nt][0], acc2[mi][nt][1]);
            *(float2*)(xbw + SMEM_SWZ128(r2*128 + c*4)) =
                make_float2(acc2[mi][nt][2], acc2[mi][nt][3]);
        }
    __syncwarp();

    // layer 3: 32 -> 16, relu, * tmask  -> smm (smem, not global)
    {
        uint32_t wf[4][2][2];
        float bv[2][2];
        #pragma unroll
        for (int ks = 0; ks < 4; ks++)
            #pragma unroll
            for (int nt = 0; nt < 2; nt++) {
                int k = ks * 8 + kk, n = nt * 8 + gg;
                wf[ks][nt][0] = __float_as_uint(to_tf32(w3[k * CMID + n]));
                wf[ks][nt][1] = __float_as_uint(to_tf32(w3[(k + 4) * CMID + n]));
            }
        #pragma unroll
        for (int nt = 0; nt < 2; nt++) {
            int c = nt * 8 + kk * 2;
            bv[nt][0] = b3[c]; bv[nt][1] = b3[c + 1];
        }
        float acc3[2][2][4];
        #pragma unroll
        for (int mi = 0; mi < 2; mi++)
            #pragma unroll
            for (int nt = 0; nt < 2; nt++)
                acc3[mi][nt][0] = acc3[mi][nt][1] = acc3[mi][nt][2] = acc3[mi][nt][3] = 0.f;
        #pragma unroll
        for (int ks = 0; ks < 4; ks++) {
            uint32_t a[2][4];
            #pragma unroll
            for (int mi = 0; mi < 2; mi++) {
                uint32_t addr = xb + SMEM_SWZ128((mi*16 + a_row)*128 + ks*32 + a_hi);
                LDSM4(a[mi][0], a[mi][1], a[mi][2], a[mi][3], addr);
            }
            #pragma unroll
            for (int mi = 0; mi < 2; mi++)
                #pragma unroll
                for (int nt = 0; nt < 2; nt++)
                    MMA_TF32(acc3[mi][nt], a[mi], wf[ks][nt]);
        }
        const int r0l = wid * 32;   // local pair base within block
        #pragma unroll
        for (int mi = 0; mi < 2; mi++)
            #pragma unroll
            for (int nt = 0; nt < 2; nt++) {
                int c = nt * 8 + kk * 2;
                int r1 = r0l + mi*16 + gg, r2 = r1 + 8;
                float2 v1 = { fmaxf(acc3[mi][nt][0] + bv[nt][0], 0.f) * tmr[mi][0],
                              fmaxf(acc3[mi][nt][1] + bv[nt][1], 0.f) * tmr[mi][0] };
                float2 v2 = { fmaxf(acc3[mi][nt][2] + bv[nt][0], 0.f) * tmr[mi][1],
                              fmaxf(acc3[mi][nt][3] + bv[nt][1], 0.f) * tmr[mi][1] };
                *(float2*)(smm + (r1 >> 4) * SMM_STRIDE + (r1 & 15) * CMID + c) = v1;
                *(float2*)(smm + (r2 >> 4) * SMM_STRIDE + (r2 & 15) * CMID + c) = v2;
            }
    }
    __syncthreads();   // all warps done with xbuf + smm populated

    // ---- phase 2: einsum (sff overlaps dead xbuf region) ----
    {
        const int pt = t >> 4;           // point slot 0..7
        const int j  = t & 15;           // neighbor / c-quad slot
        const int p2  = blockIdx.x * 8 + pt;
        const int pr2 = p2 * KK + j;
        const int q2  = (p2 / NN) * NN + g_idxs[pr2];
        const float tm2 = mask[q2];

        {
            const float4* fr = (const float4*)(feats + (size_t)q2 * CIN);
            float4* dst = (float4*)(pool + pt * SFF_STRIDE + j * CIN);
            #pragma unroll
            for (int c4 = 0; c4 < CIN / 4; c4++) {
                float4 v = fr[c4];
                v.x *= tm2; v.y *= tm2; v.z *= tm2; v.w *= tm2;
                dst[c4] = v;
            }
        }
        __syncthreads();

        float acc[CMID][4];
        #pragma unroll
        for (int m2 = 0; m2 < CMID; m2++)
            acc[m2][0] = acc[m2][1] = acc[m2][2] = acc[m2][3] = 0.f;

        const float4* sfp = (const float4*)(pool + pt * SFF_STRIDE);
        const float4* smp = (const float4*)(smm + pt * SMM_STRIDE);
        #pragma unroll
        for (int k2 = 0; k2 < KK; k2++) {
            float4 f  = sfp[k2 * (CIN / 4) + j];
            float4 m0 = smp[k2 * 4 + 0];
            float4 m1 = smp[k2 * 4 + 1];
            float4 m2v = smp[k2 * 4 + 2];
            float4 m3 = smp[k2 * 4 + 3];
            const float mv[CMID] = {m0.x,m0.y,m0.z,m0.w, m1.x,m1.y,m1.z,m1.w,
                                    m2v.x,m2v.y,m2v.z,m2v.w, m3.x,m3.y,m3.z,m3.w};
            #pragma unroll
            for (int m2 = 0; m2 < CMID; m2++) {
                acc[m2][0] += mv[m2] * f.x; acc[m2][1] += mv[m2] * f.y;
                acc[m2][2] += mv[m2] * f.z; acc[m2][3] += mv[m2] * f.w;
            }
        }
        float4* Ep = (float4*)(g_E + (size_t)p2 * EDIM);
        #pragma unroll
        for (int m2 = 0; m2 < CMID; m2++) {
            float4 v = {to_tf32(acc[m2][0]), to_tf32(acc[m2][1]),
                        to_tf32(acc[m2][2]), to_tf32(acc[m2][3])};
            Ep[m2 * (CIN / 4) + j] = v;
        }
    }
}

// ---------------------------------------------------------------------------
// Kernel 3 (fused, mma.sync tf32) — R11 config (proven):
//   H = relu(E @ f1 + fb1)  -> smem ;  out = H @ f2 + fb2
// CTA: 128 rows x N=256, 256 threads (8 warps), cp.async double buffer.
// ---------------------------------------------------------------------------
#define SA(s) ((s) * 49152)
#define SB(s) ((s) * 49152 + 16384)
#define HS_OFF 0
#define F2_OFF 131072
#define SMT 196608

__global__ void __launch_bounds__(256, 1) k_mma(
    const float* __restrict__ fb1, const float* __restrict__ fb2,
    float* __restrict__ out)
{
    extern __shared__ char sm[];
    const uint32_t sb = smem_u32(sm);
    const int t = threadIdx.x;
    const int lane = t & 31;
    const int wid  = t >> 5;
    const int row0 = blockIdx.x * 128;

    const int wm = wid >> 2;
    const int wn = wid & 3;

    const int a_row  = lane & 15;
    const int a_k16  = (lane >> 4) * 16;
    const int b_noff = (lane & 7) + ((lane & 16) >> 1);
    const int b_k16  = (lane & 8) * 2;

    float acc[4][8][4];
    #pragma unroll
    for (int i = 0; i < 4; i++)
        #pragma unroll
        for (int j = 0; j < 8; j++)
            acc[i][j][0] = acc[i][j][1] = acc[i][j][2] = acc[i][j][3] = 0.f;

    {
        #pragma unroll
        for (int s = 0; s < 4; s++) {
            int u = t + s * 256;  int r = u >> 3, c = u & 7;
            cpa16(sb + SA(0) + SMEM_SWZ128(r * 128 + c * 16),
                  g_E + (size_t)(row0 + r) * EDIM + c * 4);
        }
        #pragma unroll
        for (int s = 0; s < 8; s++) {
            int u = t + s * 256;  int n = u >> 3, c = u & 7;
            cpa16(sb + SB(0) + SMEM_SWZ128(n * 128 + c * 16),
                  g_f1T + (size_t)n * EDIM + c * 4);
        }
        CP_COMMIT();
    }

    for (int i = 0; i < 32; i++) {
        const int buf = i & 1;
        if (i < 31) {
            const int kc = (i + 1) * 32;
            const int nb = buf ^ 1;
            #pragma unroll
            for (int s = 0; s < 4; s++) {
                int u = t + s * 256;  int r = u >> 3, c = u & 7;
                cpa16(sb + SA(nb) + SMEM_SWZ128(r * 128 + c * 16),
                      g_E + (size_t)(row0 + r) * EDIM + kc + c * 4);
            }
            #pragma unroll
            for (int s = 0; s < 8; s++) {
                int u = t + s * 256;  int n = u >> 3, c = u & 7;
                cpa16(sb + SB(nb) + SMEM_SWZ128(n * 128 + c * 16),
                      g_f1T + (size_t)n * EDIM + kc + c * 4);
            }
            CP_COMMIT();
            CP_WAIT1();
        } else {
            CP_WAIT0();
        }
        __syncthreads();

        const uint32_t Ab = sb + SA(buf);
        const uint32_t Bb = sb + SB(buf);
        #pragma unroll
        for (int k8 = 0; k8 < 4; k8++) {
            uint32_t a[4][4];
            #pragma unroll
            for (int mi = 0; mi < 4; mi++) {
                uint32_t addr = Ab + SMEM_SWZ128(
                    (wm * 64 + mi * 16 + a_row) * 128 + k8 * 32 + a_k16);
                LDSM4(a[mi][0], a[mi][1], a[mi][2], a[mi][3], addr);
            }
            uint32_t bf[8][2];
            #pragma unroll
            for (int jj = 0; jj < 4; jj++) {
                uint32_t r0, r1, r2, r3;
                uint32_t addr = Bb + SMEM_SWZ128(
                    (wn * 64 + jj * 16 + b_noff) * 128 + k8 * 32 + b_k16);
                LDSM4(r0, r1, r2, r3, addr);
                bf[2*jj][0] = r0; bf[2*jj][1] = r1;
                bf[2*jj+1][0] = r2; bf[2*jj+1][1] = r3;
            }
            #pragma unroll
            for (int mi = 0; mi < 4; mi++)
                #pragma unroll
                for (int j = 0; j < 8; j++)
                    MMA_TF32(acc[mi][j], a[mi], bf[j]);
        }
        __syncthreads();
    }

    const int qrow = lane >> 2;
    const int qcol = (lane & 3) * 2;
    #pragma unroll
    for (int mi = 0; mi < 4; mi++) {
        #pragma unroll
        for (int j = 0; j < 8; j++) {
            const int col = wn * 64 + j * 8 + qcol;
            const float bv0 = __ldg(fb1 + col);
            const float bv1 = __ldg(fb1 + col + 1);
            const int r01 = wm * 64 + mi * 16 + qrow;
            const int r23 = r01 + 8;
            float2 h01 = { to_tf32(fmaxf(acc[mi][j][0] + bv0, 0.f)),
                           to_tf32(fmaxf(acc[mi][j][1] + bv1, 0.f)) };
            float2 h23 = { to_tf32(fmaxf(acc[mi][j][2] + bv0, 0.f)),
                           to_tf32(fmaxf(acc[mi][j][3] + bv1, 0.f)) };
            *(float2*)(sm + HS_OFF + swz2(r01, col >> 2) + (col & 3) * 4) = h01;
            *(float2*)(sm + HS_OFF + swz2(r23, col >> 2) + (col & 3) * 4) = h23;
        }
    }
    #pragma unroll
    for (int s = 0; s < 16; s++) {
        int u = t + s * 256;
        int n = u >> 6, c4 = u & 63;
        float4 v = *(const float4*)(g_f2T + (size_t)n * FH1 + c4 * 4);
        *(float4*)(sm + F2_OFF + swz2(n, c4)) = v;
    }
    __syncthreads();

    const int wm2 = wid >> 1;
    const int wn2 = wid & 1;
    float acc2[2][4][4];
    #pragma unroll
    for (int i = 0; i < 2; i++)
        #pragma unroll
        for (int j = 0; j < 4; j++)
            acc2[i][j][0] = acc2[i][j][1] = acc2[i][j][2] = acc2[i][j][3] = 0.f;

    #pragma unroll 4
    for (int k8 = 0; k8 < 32; k8++) {
        uint32_t a2[2][4];
        #pragma unroll
        for (int mi = 0; mi < 2; mi++) {
            uint32_t addr = sb + HS_OFF +
                swz2(wm2 * 32 + mi * 16 + a_row, k8 * 2 + (lane >> 4));
            LDSM4(a2[mi][0], a2[mi][1], a2[mi][2], a2[mi][3], addr);
        }
        uint32_t b2[4][2];
        #pragma unroll
        for (int jj = 0; jj < 2; jj++) {
            uint32_t r0, r1, r2, r3;
            uint32_t addr = sb + F2_OFF +
                swz2(wn2 * 32 + jj * 16 + b_noff, k8 * 2 + ((lane >> 3) & 1));
            LDSM4(r0, r1, r2, r3, addr);
            b2[2*jj][0] = r0; b2[2*jj][1] = r1;
            b2[2*jj+1][0] = r2; b2[2*jj+1][1] = r3;
        }
        #pragma unroll
        for (int mi = 0; mi < 2; mi++)
            #pragma unroll
            for (int j = 0; j < 4; j++)
                MMA_TF32(acc2[mi][j], a2[mi], b2[j]);
    }

    #pragma unroll
    for (int mi = 0; mi < 2; mi++) {
        #pragma unroll
        for (int j = 0; j < 4; j++) {
            const int col = wn2 * 32 + j * 8 + qcol;
            const float bv0 = __ldg(fb2 + col);
            const float bv1 = __ldg(fb2 + col + 1);
            const int row = row0 + wm2 * 32 + mi * 16 + qrow;
            float2 o01 = { acc2[mi][j][0] + bv0, acc2[mi][j][1] + bv1 };
            float2 o23 = { acc2[mi][j][2] + bv0, acc2[mi][j][3] + bv1 };
            *(float2*)(out + (size_t)row * COUT + col) = o01;
            *(float2*)(out + (size_t)(row + 8) * COUT + col) = o23;
        }
    }
}

// ---------------------------------------------------------------------------
extern "C" void kernel_launch(void* const* d_in, const int* in_sizes, int n_in,
                              void* d_out, int out_size) {
    const int*   groups = (const int*)  d_in[0];
    const float* points = (const float*)d_in[1];
    const float* feats  = (const float*)d_in[2];
    const float* pmask  = (const float*)d_in[3];
    const float* w1 = (const float*)d_in[4];
    const float* b1 = (const float*)d_in[5];
    const float* w2 = (const float*)d_in[6];
    const float* b2 = (const float*)d_in[7];
    const float* w3 = (const float*)d_in[8];
    const float* b3 = (const float*)d_in[9];
    const float* f1  = (const float*)d_in[10];
    const float* fb1 = (const float*)d_in[11];
    const float* f2  = (const float*)d_in[12];
    const float* fb2 = (const float*)d_in[13];
    float* out = (float*)d_out;

    cudaFuncSetAttribute(k_mma, cudaFuncAttributeMaxDynamicSharedMemorySize, SMT);

    k_prep<<<528, 256>>>(groups, f1, f2);
    k_mlpe<<<NPAIR / 128, 128>>>(points, feats, pmask,
                                 w1, b1, w2, b2, w3, b3);
    k_mma<<<NPTS / 128, 256, SMT>>>(fb1, fb2, out);
}